// round 1
// baseline (speedup 1.0000x reference)
#include <cuda_runtime.h>
#include <cuda_bf16.h>

// BarlowTwinsLoss: loss = sum_d (1 - clip(c_d))^2 where
//   c_d = (S_et - S_e*S_t/N) / (std_e * std_t * (N+eps))
//   std  = max(sqrt((S_xx - S_x^2/N)/(N-1)), eps)
// Pure HBM-bound reduction: 256 MB read -> 5 column sums -> scalar.

static constexpr int NROWS = 16384;
static constexpr int DCOLS = 2048;
static constexpr int GY    = 256;                 // row chunks
static constexpr int RPB   = NROWS / GY;          // 64 rows per block
static constexpr int K2_BLOCKS  = 16;
static constexpr int K2_THREADS = 128;            // 16*128 = 2048 columns

// Scratch: partial sums [stat][row-chunk][column]. 5*256*2048*4B = 10.5 MB.
__device__ float  g_part[5][GY][DCOLS];
__device__ double g_blockpart[K2_BLOCKS];

// ---------------------------------------------------------------------------
// k1: column-wise partial sums. grid (2, GY), 256 thr. Thread owns 4 columns.
// ---------------------------------------------------------------------------
__global__ void __launch_bounds__(256)
k1_partials(const float* __restrict__ E, const float* __restrict__ T) {
    const int c  = blockIdx.x * 1024 + threadIdx.x * 4;   // column base (mult of 4)
    const int gy = blockIdx.y;
    const long long r0 = (long long)gy * RPB;

    const float4* __restrict__ ep =
        reinterpret_cast<const float4*>(E + r0 * DCOLS + c);
    const float4* __restrict__ tp =
        reinterpret_cast<const float4*>(T + r0 * DCOLS + c);
    const int stride4 = DCOLS / 4;   // float4 per row

    float4 se  = make_float4(0.f, 0.f, 0.f, 0.f);
    float4 see = se, st = se, stt = se, sc = se;

    #pragma unroll 4
    for (int r = 0; r < RPB; ++r) {
        float4 ev = ep[(long long)r * stride4];
        float4 tv = tp[(long long)r * stride4];

        se.x  += ev.x;  se.y  += ev.y;  se.z  += ev.z;  se.w  += ev.w;
        st.x  += tv.x;  st.y  += tv.y;  st.z  += tv.z;  st.w  += tv.w;
        see.x = fmaf(ev.x, ev.x, see.x);
        see.y = fmaf(ev.y, ev.y, see.y);
        see.z = fmaf(ev.z, ev.z, see.z);
        see.w = fmaf(ev.w, ev.w, see.w);
        stt.x = fmaf(tv.x, tv.x, stt.x);
        stt.y = fmaf(tv.y, tv.y, stt.y);
        stt.z = fmaf(tv.z, tv.z, stt.z);
        stt.w = fmaf(tv.w, tv.w, stt.w);
        sc.x  = fmaf(ev.x, tv.x, sc.x);
        sc.y  = fmaf(ev.y, tv.y, sc.y);
        sc.z  = fmaf(ev.z, tv.z, sc.z);
        sc.w  = fmaf(ev.w, tv.w, sc.w);
    }

    *reinterpret_cast<float4*>(&g_part[0][gy][c]) = se;
    *reinterpret_cast<float4*>(&g_part[1][gy][c]) = see;
    *reinterpret_cast<float4*>(&g_part[2][gy][c]) = st;
    *reinterpret_cast<float4*>(&g_part[3][gy][c]) = stt;
    *reinterpret_cast<float4*>(&g_part[4][gy][c]) = sc;
}

// ---------------------------------------------------------------------------
// k2: reduce partials per column, finalize c_d, (1-c)^2, block tree-reduce.
// ---------------------------------------------------------------------------
__global__ void __launch_bounds__(K2_THREADS)
k2_finalize() {
    const int col = blockIdx.x * K2_THREADS + threadIdx.x;

    float s0 = 0.f, s1 = 0.f, s2 = 0.f, s3 = 0.f, s4 = 0.f;
    #pragma unroll 4
    for (int g = 0; g < GY; ++g) {
        s0 += g_part[0][g][col];
        s1 += g_part[1][g][col];
        s2 += g_part[2][g][col];
        s3 += g_part[3][g][col];
        s4 += g_part[4][g][col];
    }

    const double n   = (double)NROWS;
    const double eps = 1e-9;
    double se = s0, see = s1, st = s2, stt = s3, sc = s4;

    double vare = (see - se * se / n) / (n - 1.0);
    double vart = (stt - st * st / n) / (n - 1.0);
    double stde = fmax(sqrt(fmax(vare, 0.0)), eps);
    double stdt = fmax(sqrt(fmax(vart, 0.0)), eps);
    double cross = sc - se * st / n;
    double c = cross / (stde * stdt) / (n + eps);
    c = fmin(fmax(c, -1.0 + eps), 1.0 - eps);
    double term = (1.0 - c) * (1.0 - c);

    __shared__ double sh[K2_THREADS];
    sh[threadIdx.x] = term;
    __syncthreads();
    #pragma unroll
    for (int off = K2_THREADS / 2; off > 0; off >>= 1) {
        if (threadIdx.x < off) sh[threadIdx.x] += sh[threadIdx.x + off];
        __syncthreads();
    }
    if (threadIdx.x == 0) g_blockpart[blockIdx.x] = sh[0];
}

// ---------------------------------------------------------------------------
// k3: deterministic final sum of 16 block partials -> scalar output.
// ---------------------------------------------------------------------------
__global__ void k3_final(float* __restrict__ out) {
    double acc = 0.0;
    #pragma unroll
    for (int i = 0; i < K2_BLOCKS; ++i) acc += g_blockpart[i];
    out[0] = (float)acc;
}

extern "C" void kernel_launch(void* const* d_in, const int* in_sizes, int n_in,
                              void* d_out, int out_size) {
    const float* E = (const float*)d_in[0];   // e_q  [16384, 2048] fp32
    const float* T = (const float*)d_in[1];   // tau  [16384, 2048] fp32
    float* out = (float*)d_out;

    dim3 g1(DCOLS / 1024, GY);   // (2, 256)
    k1_partials<<<g1, 256>>>(E, T);
    k2_finalize<<<K2_BLOCKS, K2_THREADS>>>();
    k3_final<<<1, 1>>>(out);
}

// round 2
// speedup vs baseline: 1.5431x; 1.5431x over previous
#include <cuda_runtime.h>
#include <cuda_bf16.h>

// BarlowTwinsLoss: loss = sum_d (1 - clip(c_d))^2 where
//   c_d = (S_et - S_e*S_t/N) / (std_e * std_t * (N+eps))
//   std  = max(sqrt((S_xx - S_x^2/N)/(N-1)), eps)
// HBM-bound reduction: 256 MB read -> 5 column sums -> scalar.

static constexpr int NROWS = 16384;
static constexpr int DCOLS = 2048;
static constexpr int GY    = 256;                 // row chunks
static constexpr int RPB   = NROWS / GY;          // 64 rows per block

static constexpr int K2_BLOCKS   = DCOLS / 32;    // 64 blocks, 32 cols each
static constexpr int K2_WARPS    = 8;             // chunks split across 8 warps
static constexpr int K2_GPW      = GY / K2_WARPS; // 32 chunks per warp

// Scratch: partial sums [stat][row-chunk][column]. 5*256*2048*4B = 10.5 MB.
__device__ float  g_part[5][GY][DCOLS];
__device__ double g_blockpart[K2_BLOCKS];

// ---------------------------------------------------------------------------
// k1: column-wise partial sums. grid (2, GY), 256 thr. Thread owns 4 columns.
// ---------------------------------------------------------------------------
__global__ void __launch_bounds__(256)
k1_partials(const float* __restrict__ E, const float* __restrict__ T) {
    const int c  = blockIdx.x * 1024 + threadIdx.x * 4;   // column base (mult of 4)
    const int gy = blockIdx.y;
    const long long r0 = (long long)gy * RPB;

    const float4* __restrict__ ep =
        reinterpret_cast<const float4*>(E + r0 * DCOLS + c);
    const float4* __restrict__ tp =
        reinterpret_cast<const float4*>(T + r0 * DCOLS + c);
    const int stride4 = DCOLS / 4;   // float4 per row

    float4 se  = make_float4(0.f, 0.f, 0.f, 0.f);
    float4 see = se, st = se, stt = se, sc = se;

    #pragma unroll 8
    for (int r = 0; r < RPB; ++r) {
        float4 ev = __ldcs(&ep[(long long)r * stride4]);
        float4 tv = __ldcs(&tp[(long long)r * stride4]);

        se.x  += ev.x;  se.y  += ev.y;  se.z  += ev.z;  se.w  += ev.w;
        st.x  += tv.x;  st.y  += tv.y;  st.z  += tv.z;  st.w  += tv.w;
        see.x = fmaf(ev.x, ev.x, see.x);
        see.y = fmaf(ev.y, ev.y, see.y);
        see.z = fmaf(ev.z, ev.z, see.z);
        see.w = fmaf(ev.w, ev.w, see.w);
        stt.x = fmaf(tv.x, tv.x, stt.x);
        stt.y = fmaf(tv.y, tv.y, stt.y);
        stt.z = fmaf(tv.z, tv.z, stt.z);
        stt.w = fmaf(tv.w, tv.w, stt.w);
        sc.x  = fmaf(ev.x, tv.x, sc.x);
        sc.y  = fmaf(ev.y, tv.y, sc.y);
        sc.z  = fmaf(ev.z, tv.z, sc.z);
        sc.w  = fmaf(ev.w, tv.w, sc.w);
    }

    *reinterpret_cast<float4*>(&g_part[0][gy][c]) = se;
    *reinterpret_cast<float4*>(&g_part[1][gy][c]) = see;
    *reinterpret_cast<float4*>(&g_part[2][gy][c]) = st;
    *reinterpret_cast<float4*>(&g_part[3][gy][c]) = stt;
    *reinterpret_cast<float4*>(&g_part[4][gy][c]) = sc;
}

// ---------------------------------------------------------------------------
// k2: reduce partials per column, finalize c_d, (1-c)^2, block tree-reduce.
// 64 blocks x 256 threads. Warp w handles chunks [w*32, w*32+32) for the
// block's 32 consecutive columns -> all loads are 128B coalesced.
// ---------------------------------------------------------------------------
__global__ void __launch_bounds__(256)
k2_reduce() {
    const int lane = threadIdx.x & 31;
    const int w    = threadIdx.x >> 5;            // 0..7
    const int col  = blockIdx.x * 32 + lane;

    float s0 = 0.f, s1 = 0.f, s2 = 0.f, s3 = 0.f, s4 = 0.f;
    const int g0 = w * K2_GPW;
    #pragma unroll 8
    for (int g = g0; g < g0 + K2_GPW; ++g) {
        s0 += g_part[0][g][col];
        s1 += g_part[1][g][col];
        s2 += g_part[2][g][col];
        s3 += g_part[3][g][col];
        s4 += g_part[4][g][col];
    }

    __shared__ float sh[5][K2_WARPS][32];
    sh[0][w][lane] = s0;
    sh[1][w][lane] = s1;
    sh[2][w][lane] = s2;
    sh[3][w][lane] = s3;
    sh[4][w][lane] = s4;
    __syncthreads();

    if (w == 0) {
        float S[5];
        #pragma unroll
        for (int si = 0; si < 5; ++si) {
            float acc = sh[si][0][lane];
            #pragma unroll
            for (int k = 1; k < K2_WARPS; ++k) acc += sh[si][k][lane];
            S[si] = acc;
        }

        const double n   = (double)NROWS;
        const double eps = 1e-9;
        double se = S[0], see = S[1], st = S[2], stt = S[3], sc = S[4];

        double vare = (see - se * se / n) / (n - 1.0);
        double vart = (stt - st * st / n) / (n - 1.0);
        double stde = fmax(sqrt(fmax(vare, 0.0)), eps);
        double stdt = fmax(sqrt(fmax(vart, 0.0)), eps);
        double cross = sc - se * st / n;
        double c = cross / (stde * stdt) / (n + eps);
        c = fmin(fmax(c, -1.0 + eps), 1.0 - eps);
        double term = (1.0 - c) * (1.0 - c);

        // deterministic fixed-pattern warp tree over the 32 column terms
        #pragma unroll
        for (int off = 16; off > 0; off >>= 1)
            term += __shfl_down_sync(0xffffffffu, term, off);

        if (lane == 0) g_blockpart[blockIdx.x] = term;
    }
}

// ---------------------------------------------------------------------------
// k3: deterministic final sum of 64 block partials -> scalar output.
// ---------------------------------------------------------------------------
__global__ void k3_final(float* __restrict__ out) {
    double acc = 0.0;
    #pragma unroll
    for (int i = 0; i < K2_BLOCKS; ++i) acc += g_blockpart[i];
    out[0] = (float)acc;
}

extern "C" void kernel_launch(void* const* d_in, const int* in_sizes, int n_in,
                              void* d_out, int out_size) {
    const float* E = (const float*)d_in[0];   // e_q  [16384, 2048] fp32
    const float* T = (const float*)d_in[1];   // tau  [16384, 2048] fp32
    float* out = (float*)d_out;

    dim3 g1(DCOLS / 1024, GY);   // (2, 256)
    k1_partials<<<g1, 256>>>(E, T);
    k2_reduce<<<K2_BLOCKS, 256>>>();
    k3_final<<<1, 1>>>(out);
}

// round 3
// speedup vs baseline: 1.5919x; 1.0316x over previous
#include <cuda_runtime.h>
#include <cuda_bf16.h>

// BarlowTwinsLoss, fully fused single kernel.
//   loss = sum_d (1 - clip(c_d))^2,
//   c_d = (S_et - S_e*S_t/N) / (std_e*std_t*(N+eps))
// Phase 1: 512 co-resident blocks compute column partial sums (HBM-bound).
// Phase 2: first 64 blocks spin until all partials land (L2-resident), reduce.
// Phase 3: last phase-2 block sums 64 doubles in fixed order -> out[0].

static constexpr int NROWS = 16384;
static constexpr int DCOLS = 2048;
static constexpr int GY    = 256;                 // row chunks
static constexpr int RPB   = NROWS / GY;          // 64 rows per block
static constexpr int NBLK  = 2 * GY;              // 512 total blocks

static constexpr int P2_BLOCKS = DCOLS / 32;      // 64 phase-2 blocks
static constexpr int P2_WARPS  = 8;
static constexpr int P2_GPW    = GY / P2_WARPS;   // 32 chunks per warp

// Scratch (static device globals; no allocation). 5*256*2048*4B = 10.5 MB.
__device__ float  g_part[5][GY][DCOLS];
__device__ double g_blockpart[P2_BLOCKS];
__device__ int    g_cnt1 = 0;
__device__ int    g_cnt2 = 0;

__global__ void __launch_bounds__(256)
barlow_fused(const float* __restrict__ E, const float* __restrict__ T,
             float* __restrict__ out) {
    const int flat = blockIdx.y * 2 + blockIdx.x;     // 0..511
    const int c    = blockIdx.x * 1024 + threadIdx.x * 4;
    const int gy   = blockIdx.y;
    const long long r0 = (long long)gy * RPB;

    // ---------------- Phase 1: column partial sums -------------------------
    {
        const float4* __restrict__ ep =
            reinterpret_cast<const float4*>(E + r0 * DCOLS + c);
        const float4* __restrict__ tp =
            reinterpret_cast<const float4*>(T + r0 * DCOLS + c);
        const int stride4 = DCOLS / 4;

        float4 se  = make_float4(0.f, 0.f, 0.f, 0.f);
        float4 see = se, st = se, stt = se, sc = se;

        #pragma unroll 8
        for (int r = 0; r < RPB; ++r) {
            float4 ev = __ldcs(&ep[(long long)r * stride4]);
            float4 tv = __ldcs(&tp[(long long)r * stride4]);

            se.x  += ev.x;  se.y  += ev.y;  se.z  += ev.z;  se.w  += ev.w;
            st.x  += tv.x;  st.y  += tv.y;  st.z  += tv.z;  st.w  += tv.w;
            see.x = fmaf(ev.x, ev.x, see.x);
            see.y = fmaf(ev.y, ev.y, see.y);
            see.z = fmaf(ev.z, ev.z, see.z);
            see.w = fmaf(ev.w, ev.w, see.w);
            stt.x = fmaf(tv.x, tv.x, stt.x);
            stt.y = fmaf(tv.y, tv.y, stt.y);
            stt.z = fmaf(tv.z, tv.z, stt.z);
            stt.w = fmaf(tv.w, tv.w, stt.w);
            sc.x  = fmaf(ev.x, tv.x, sc.x);
            sc.y  = fmaf(ev.y, tv.y, sc.y);
            sc.z  = fmaf(ev.z, tv.z, sc.z);
            sc.w  = fmaf(ev.w, tv.w, sc.w);
        }

        *reinterpret_cast<float4*>(&g_part[0][gy][c]) = se;
        *reinterpret_cast<float4*>(&g_part[1][gy][c]) = see;
        *reinterpret_cast<float4*>(&g_part[2][gy][c]) = st;
        *reinterpret_cast<float4*>(&g_part[3][gy][c]) = stt;
        *reinterpret_cast<float4*>(&g_part[4][gy][c]) = sc;
    }

    // Publish phase-1 completion.
    __syncthreads();
    if (threadIdx.x == 0) {
        __threadfence();
        atomicAdd(&g_cnt1, 1);
    }

    if (flat >= P2_BLOCKS) return;   // non-designated blocks are done

    // ---------------- Phase 2: per-column reduce + finalize ----------------
    if (threadIdx.x == 0) {
        while (*(volatile int*)&g_cnt1 < NBLK) __nanosleep(64);
    }
    __syncthreads();
    __threadfence();                 // acquire: see all g_part writes

    const int lane = threadIdx.x & 31;
    const int w    = threadIdx.x >> 5;
    const int col  = flat * 32 + lane;

    float s0 = 0.f, s1 = 0.f, s2 = 0.f, s3 = 0.f, s4 = 0.f;
    const int g0 = w * P2_GPW;
    #pragma unroll 8
    for (int g = g0; g < g0 + P2_GPW; ++g) {
        s0 += g_part[0][g][col];
        s1 += g_part[1][g][col];
        s2 += g_part[2][g][col];
        s3 += g_part[3][g][col];
        s4 += g_part[4][g][col];
    }

    __shared__ float sh[5][P2_WARPS][32];
    sh[0][w][lane] = s0;
    sh[1][w][lane] = s1;
    sh[2][w][lane] = s2;
    sh[3][w][lane] = s3;
    sh[4][w][lane] = s4;
    __syncthreads();

    if (w == 0) {
        float S[5];
        #pragma unroll
        for (int si = 0; si < 5; ++si) {
            float acc = sh[si][0][lane];
            #pragma unroll
            for (int k = 1; k < P2_WARPS; ++k) acc += sh[si][k][lane];
            S[si] = acc;
        }

        const double n   = (double)NROWS;
        const double eps = 1e-9;
        double se = S[0], see = S[1], st = S[2], stt = S[3], sc = S[4];

        double vare = (see - se * se / n) / (n - 1.0);
        double vart = (stt - st * st / n) / (n - 1.0);
        double stde = fmax(sqrt(fmax(vare, 0.0)), eps);
        double stdt = fmax(sqrt(fmax(vart, 0.0)), eps);
        double cross = sc - se * st / n;
        double cc = cross / (stde * stdt) / (n + eps);
        cc = fmin(fmax(cc, -1.0 + eps), 1.0 - eps);
        double term = (1.0 - cc) * (1.0 - cc);

        #pragma unroll
        for (int off = 16; off > 0; off >>= 1)
            term += __shfl_down_sync(0xffffffffu, term, off);

        // ---------------- Phase 3: final scalar ----------------------------
        if (lane == 0) {
            g_blockpart[flat] = term;
            __threadfence();
            int old = atomicAdd(&g_cnt2, 1);
            if (old == P2_BLOCKS - 1) {
                __threadfence();
                double acc = 0.0;
                #pragma unroll
                for (int i = 0; i < P2_BLOCKS; ++i) acc += g_blockpart[i];
                out[0] = (float)acc;
                // reset counters for the next graph replay (after all uses)
                __threadfence();
                g_cnt1 = 0;
                g_cnt2 = 0;
            }
        }
    }
}

extern "C" void kernel_launch(void* const* d_in, const int* in_sizes, int n_in,
                              void* d_out, int out_size) {
    const float* E = (const float*)d_in[0];   // e_q  [16384, 2048] fp32
    const float* T = (const float*)d_in[1];   // tau  [16384, 2048] fp32
    float* out = (float*)d_out;

    dim3 grid(2, GY);   // 512 blocks, all co-resident (4/SM * 148 = 592 slots)
    barlow_fused<<<grid, 256>>>(E, T, out);
}